// round 2
// baseline (speedup 1.0000x reference)
#include <cuda_runtime.h>
#include <math.h>

#define Nn 100000
#define Ee 1600000
#define Hh 64
#define NHEADS 4
#define CC 256           // NHEADS * Hh
#define EPSN 1e-5f

// ---------------- scratch (device bss, no allocation) ----------------
__device__ __align__(16) float d_nacc[Nn * 8];        // deg, agg[5], easum[2]
__device__ __align__(16) float d_h[Nn * Hh];
__device__ __align__(16) float d_la[Nn * 2];
__device__ float d_sum1[2 * Hh];
__device__ float d_mu1[Hh], d_sc1[Hh];
__device__ __align__(16) float d_wT[Hh * CC];          // transposed gat_w: [k][t]
__device__ float d_weff[NHEADS * 2];
__device__ __align__(16) float d_xp[Nn * CC];
__device__ __align__(16) float d_asrc[Nn * NHEADS];
__device__ __align__(16) float d_adst[Nn * NHEADS];
__device__ __align__(16) float d_es[Nn * NHEADS];      // exp(alpha_self)
__device__ __align__(16) float d_den[Nn * NHEADS];     // softmax denominator
__device__ __align__(16) float d_expa[Ee * NHEADS];
__device__ __align__(16) float d_gnum[Nn * CC];
__device__ __align__(16) float d_g[Nn * CC];
__device__ float d_sum2[2 * CC];
__device__ float d_mu2[CC], d_sc2[CC];

// ---------------- helpers ----------------
__device__ __forceinline__ void red_add_v4(float* addr, float a, float b, float c, float d) {
    asm volatile("red.global.add.v4.f32 [%0], {%1,%2,%3,%4};"
                 :: "l"(addr), "f"(a), "f"(b), "f"(c), "f"(d) : "memory");
}
__device__ __forceinline__ float lrelu(float a) { return a > 0.f ? a : 0.2f * a; }
__device__ __forceinline__ float eluf(float a)  { return a > 0.f ? a : expm1f(a); }

// ---------------- k_prep: transpose gat_w + weff ----------------
__global__ void k_prep(const float* __restrict__ gat_w,
                       const float* __restrict__ att_e,
                       const float* __restrict__ gat_we) {
    int t = threadIdx.x;  // 256
    for (int k = 0; k < Hh; ++k)
        d_wT[k * CC + t] = gat_w[t * Hh + k];
    if (t < NHEADS * 2) {
        int h = t >> 1, kk = t & 1;
        float s = 0.f;
        for (int c = 0; c < Hh; ++c)
            s += gat_we[(h * Hh + c) * 2 + kk] * att_e[h * Hh + c];
        d_weff[t] = s;
    }
}

// ---------------- k_eagg: per-edge deg/agg/easum ----------------
__global__ void k_eagg(const int* __restrict__ src, const int* __restrict__ dst,
                       const float* __restrict__ x, const float* __restrict__ ea) {
    int e = blockIdx.x * blockDim.x + threadIdx.x;
    if (e >= Ee) return;
    int s = src[e], d = dst[e];
    const float* xs = x + s * 5;
    float x0 = xs[0], x1 = xs[1], x2 = xs[2], x3 = xs[3], x4 = xs[4];
    float2 e2 = ((const float2*)ea)[e];
    float* na = d_nacc + d * 8;
    red_add_v4(na,     1.f, x0, x1, x2);
    red_add_v4(na + 4, x3, x4, e2.x, e2.y);
}

// ---------------- k_node1: SAGE + norm1 stats ----------------
__global__ void k_node1(const float* __restrict__ x,
                        const float* __restrict__ wl,
                        const float* __restrict__ bl,
                        const float* __restrict__ wr) {
    __shared__ float sWl[Hh * 5], sWr[Hh * 5], sBl[Hh], ssum[Hh], ssum2[Hh];
    int tid = threadIdx.x;  // 256
    for (int i = tid; i < Hh * 5; i += 256) { sWl[i] = wl[i]; sWr[i] = wr[i]; }
    if (tid < Hh) { sBl[tid] = bl[tid]; ssum[tid] = 0.f; ssum2[tid] = 0.f; }
    __syncthreads();
    int nl = tid >> 6, c = tid & 63;
    int n = blockIdx.x * 4 + nl;
    float hv = 0.f;
    if (n < Nn) {
        const float* na = d_nacc + n * 8;
        float deg = fmaxf(na[0], 1.f);
        float inv = 1.f / deg;
        float a0 = na[1] * inv, a1 = na[2] * inv, a2 = na[3] * inv,
              a3 = na[4] * inv, a4 = na[5] * inv;
        const float* xr = x + n * 5;
        const float* wlr = sWl + c * 5;
        const float* wrr = sWr + c * 5;
        hv = sBl[c]
           + wlr[0]*a0 + wlr[1]*a1 + wlr[2]*a2 + wlr[3]*a3 + wlr[4]*a4
           + wrr[0]*xr[0] + wrr[1]*xr[1] + wrr[2]*xr[2] + wrr[3]*xr[3] + wrr[4]*xr[4];
        d_h[n * Hh + c] = hv;
        if (c < 2) d_la[n * 2 + c] = na[6 + c] * inv;
    }
    atomicAdd(&ssum[c], hv);
    atomicAdd(&ssum2[c], hv * hv);
    __syncthreads();
    if (tid < Hh) {
        atomicAdd(&d_sum1[tid], ssum[tid]);
        atomicAdd(&d_sum1[Hh + tid], ssum2[tid]);
    }
}

// ---------------- k_stats1 ----------------
__global__ void k_stats1(const float* __restrict__ w, const float* __restrict__ ms) {
    int c = threadIdx.x;  // 64
    float m  = d_sum1[c]      * (1.f / Nn);
    float m2 = d_sum1[Hh + c] * (1.f / Nn);
    float s = ms[c];
    float var = m2 - (2.f * s - s * s) * m * m;
    d_mu1[c] = s * m;
    d_sc1[c] = w[c] * rsqrtf(var + EPSN);
}

// ---------------- k_xp: norm1+ELU, xp = h1 @ W^T, a_src/a_dst ----------------
__global__ void k_xp(const float* __restrict__ n1b,
                     const float* __restrict__ att_s,
                     const float* __restrict__ att_d) {
    __shared__ float h1[8 * Hh];
    const int q = threadIdx.x;  // 64
    const int nb = blockIdx.x * 8;
    const float mu = d_mu1[q], sc = d_sc1[q], bb = n1b[q];
    #pragma unroll
    for (int i = 0; i < 8; ++i) {
        int n = nb + i;
        float v = 0.f;
        if (n < Nn) {
            float y = sc * (d_h[n * Hh + q] - mu) + bb;
            v = eluf(y);
        }
        h1[i * Hh + q] = v;
    }
    __syncthreads();
    float acc[8][4];
    #pragma unroll
    for (int i = 0; i < 8; ++i) { acc[i][0] = acc[i][1] = acc[i][2] = acc[i][3] = 0.f; }
    const float4* wt = (const float4*)d_wT;
    #pragma unroll 4
    for (int k = 0; k < Hh; ++k) {
        float4 w = wt[k * 64 + q];
        #pragma unroll
        for (int i = 0; i < 8; ++i) {
            float hk = h1[i * Hh + k];
            acc[i][0] = fmaf(w.x, hk, acc[i][0]);
            acc[i][1] = fmaf(w.y, hk, acc[i][1]);
            acc[i][2] = fmaf(w.z, hk, acc[i][2]);
            acc[i][3] = fmaf(w.w, hk, acc[i][3]);
        }
    }
    const int head = q >> 4;
    const int cb = (q & 15) * 4;
    float as0 = att_s[head * Hh + cb],     as1 = att_s[head * Hh + cb + 1],
          as2 = att_s[head * Hh + cb + 2], as3 = att_s[head * Hh + cb + 3];
    float ad0 = att_d[head * Hh + cb],     ad1 = att_d[head * Hh + cb + 1],
          ad2 = att_d[head * Hh + cb + 2], ad3 = att_d[head * Hh + cb + 3];
    #pragma unroll
    for (int i = 0; i < 8; ++i) {
        int n = nb + i;
        float4 o = make_float4(acc[i][0], acc[i][1], acc[i][2], acc[i][3]);
        float ps = o.x * as0 + o.y * as1 + o.z * as2 + o.w * as3;
        float pd = o.x * ad0 + o.y * ad1 + o.z * ad2 + o.w * ad3;
        #pragma unroll
        for (int off = 8; off > 0; off >>= 1) {
            ps += __shfl_xor_sync(0xffffffffu, ps, off);
            pd += __shfl_xor_sync(0xffffffffu, pd, off);
        }
        if (n < Nn) {
            ((float4*)d_xp)[n * 64 + q] = o;
            if ((q & 15) == 0) {
                d_asrc[n * NHEADS + head] = ps;
                d_adst[n * NHEADS + head] = pd;
            }
        }
    }
}

// ---------------- k_self: self-loop alpha, init denom ----------------
__global__ void k_self() {
    int n = blockIdx.x * blockDim.x + threadIdx.x;
    if (n >= Nn) return;
    float la0 = d_la[n * 2], la1 = d_la[n * 2 + 1];
    float4 as = ((const float4*)d_asrc)[n];
    float4 ad = ((const float4*)d_adst)[n];
    float4 r;
    r.x = expf(lrelu(as.x + ad.x + la0 * d_weff[0] + la1 * d_weff[1]));
    r.y = expf(lrelu(as.y + ad.y + la0 * d_weff[2] + la1 * d_weff[3]));
    r.z = expf(lrelu(as.z + ad.z + la0 * d_weff[4] + la1 * d_weff[5]));
    r.w = expf(lrelu(as.w + ad.w + la0 * d_weff[6] + la1 * d_weff[7]));
    ((float4*)d_es)[n]  = r;
    ((float4*)d_den)[n] = r;
}

// ---------------- k_alpha: per-edge exp(alpha), denom += ----------------
__global__ void k_alpha(const int* __restrict__ src, const int* __restrict__ dst,
                        const float* __restrict__ ea) {
    int e = blockIdx.x * blockDim.x + threadIdx.x;
    if (e >= Ee) return;
    int s = src[e], d = dst[e];
    float4 as = ((const float4*)d_asrc)[s];
    float4 ad = ((const float4*)d_adst)[d];
    float2 e2 = ((const float2*)ea)[e];
    float4 r;
    r.x = expf(lrelu(as.x + ad.x + e2.x * d_weff[0] + e2.y * d_weff[1]));
    r.y = expf(lrelu(as.y + ad.y + e2.x * d_weff[2] + e2.y * d_weff[3]));
    r.z = expf(lrelu(as.z + ad.z + e2.x * d_weff[4] + e2.y * d_weff[5]));
    r.w = expf(lrelu(as.w + ad.w + e2.x * d_weff[6] + e2.y * d_weff[7]));
    ((float4*)d_expa)[e] = r;
    red_add_v4(d_den + d * NHEADS, r.x, r.y, r.z, r.w);
}

// ---------------- k_msg: warp-per-edge scatter of xp[src]*expa ----------------
__global__ void k_msg(const int* __restrict__ src, const int* __restrict__ dst) {
    int e = blockIdx.x * 8 + (threadIdx.x >> 5);
    if (e >= Ee) return;
    int lane = threadIdx.x & 31;
    int s = src[e], d = dst[e];
    float exA = d_expa[e * 4 + (lane >> 4)];        // heads 0/1
    float exB = d_expa[e * 4 + 2 + (lane >> 4)];    // heads 2/3
    const float4* xs = (const float4*)(d_xp + s * CC);
    float4 vA = xs[lane];
    float4 vB = xs[lane + 32];
    float* gd = d_gnum + d * CC;
    red_add_v4(gd + lane * 4,       vA.x * exA, vA.y * exA, vA.z * exA, vA.w * exA);
    red_add_v4(gd + 128 + lane * 4, vB.x * exB, vB.y * exB, vB.z * exB, vB.w * exB);
}

// ---------------- k_g: finalize g, norm2 stats ----------------
__global__ void k_g(const float* __restrict__ gat_b) {
    int t = threadIdx.x;  // 256
    int head = t >> 6;
    float gb = gat_b[t];
    float s = 0.f, s2 = 0.f;
    int n0 = blockIdx.x * 64;
    for (int i = 0; i < 64; ++i) {
        int n = n0 + i;
        if (n >= Nn) break;
        float es = d_es[n * 4 + head];
        float den = d_den[n * 4 + head];
        float g = (d_gnum[n * CC + t] + es * d_xp[n * CC + t]) / den + gb;
        d_g[n * CC + t] = g;
        s += g; s2 += g * g;
    }
    atomicAdd(&d_sum2[t], s);
    atomicAdd(&d_sum2[CC + t], s2);
}

// ---------------- k_stats2 ----------------
__global__ void k_stats2(const float* __restrict__ w, const float* __restrict__ ms) {
    int c = threadIdx.x;  // 256
    float m  = d_sum2[c]      * (1.f / Nn);
    float m2 = d_sum2[CC + c] * (1.f / Nn);
    float s = ms[c];
    float var = m2 - (2.f * s - s * s) * m * m;
    d_mu2[c] = s * m;
    d_sc2[c] = w[c] * rsqrtf(var + EPSN);
}

// ---------------- k_out: norm2 + ELU + linear + relu ----------------
__global__ void k_out(const float* __restrict__ n2b,
                      const float* __restrict__ ow,
                      const float* __restrict__ ob,
                      float* __restrict__ out) {
    __shared__ float red[8][4];
    int n = blockIdx.x;
    int t = threadIdx.x;  // 256
    float y = d_sc2[t] * (d_g[n * CC + t] - d_mu2[t]) + n2b[t];
    y = eluf(y);
    float p0 = y * ow[t], p1 = y * ow[CC + t], p2 = y * ow[2 * CC + t], p3 = y * ow[3 * CC + t];
    #pragma unroll
    for (int off = 16; off > 0; off >>= 1) {
        p0 += __shfl_xor_sync(0xffffffffu, p0, off);
        p1 += __shfl_xor_sync(0xffffffffu, p1, off);
        p2 += __shfl_xor_sync(0xffffffffu, p2, off);
        p3 += __shfl_xor_sync(0xffffffffu, p3, off);
    }
    if ((t & 31) == 0) {
        int w = t >> 5;
        red[w][0] = p0; red[w][1] = p1; red[w][2] = p2; red[w][3] = p3;
    }
    __syncthreads();
    if (t < 4) {
        float s = ob[t];
        #pragma unroll
        for (int w = 0; w < 8; ++w) s += red[w][t];
        out[n * 4 + t] = fmaxf(s, 0.f);
    }
}

// ---------------- host ----------------
extern "C" void kernel_launch(void* const* d_in, const int* in_sizes, int n_in,
                              void* d_out, int out_size) {
    const float* x     = (const float*)d_in[0];
    const float* ea    = (const float*)d_in[1];
    const float* swl   = (const float*)d_in[2];
    const float* sbl   = (const float*)d_in[3];
    const float* swr   = (const float*)d_in[4];
    const float* n1w   = (const float*)d_in[5];
    const float* n1b   = (const float*)d_in[6];
    const float* n1ms  = (const float*)d_in[7];
    const float* gatw  = (const float*)d_in[8];
    const float* atts  = (const float*)d_in[9];
    const float* attd  = (const float*)d_in[10];
    const float* atte  = (const float*)d_in[11];
    const float* gatwe = (const float*)d_in[12];
    const float* gatb  = (const float*)d_in[13];
    const float* n2w   = (const float*)d_in[14];
    const float* n2b   = (const float*)d_in[15];
    const float* n2ms  = (const float*)d_in[16];
    const float* outw  = (const float*)d_in[17];
    const float* outb  = (const float*)d_in[18];
    const int*   eidx  = (const int*)d_in[19];
    const int* src = eidx;
    const int* dst = eidx + Ee;
    float* out = (float*)d_out;

    void *p_nacc, *p_gnum, *p_s1, *p_s2;
    cudaGetSymbolAddress(&p_nacc, d_nacc);
    cudaGetSymbolAddress(&p_gnum, d_gnum);
    cudaGetSymbolAddress(&p_s1, d_sum1);
    cudaGetSymbolAddress(&p_s2, d_sum2);
    cudaMemsetAsync(p_nacc, 0, sizeof(float) * Nn * 8);
    cudaMemsetAsync(p_gnum, 0, sizeof(float) * (size_t)Nn * CC);
    cudaMemsetAsync(p_s1, 0, sizeof(float) * 2 * Hh);
    cudaMemsetAsync(p_s2, 0, sizeof(float) * 2 * CC);

    k_prep<<<1, 256>>>(gatw, atte, gatwe);
    k_eagg<<<(Ee + 255) / 256, 256>>>(src, dst, x, ea);
    k_node1<<<(Nn + 3) / 4, 256>>>(x, swl, sbl, swr);
    k_stats1<<<1, 64>>>(n1w, n1ms);
    k_xp<<<(Nn + 7) / 8, 64>>>(n1b, atts, attd);
    k_self<<<(Nn + 255) / 256, 256>>>();
    k_alpha<<<(Ee + 255) / 256, 256>>>(src, dst, ea);
    k_msg<<<(Ee + 7) / 8, 256>>>(src, dst);
    k_g<<<(Nn + 63) / 64, 256>>>(gatb);
    k_stats2<<<1, 256>>>(n2w, n2ms);
    k_out<<<Nn, 256>>>(n2b, outw, outb, out);
}

// round 3
// speedup vs baseline: 1.0000x; 1.0000x over previous
#include <cuda_runtime.h>
#include <math.h>

#define Nn 100000
#define Ee 1600000
#define Hh 64
#define NHEADS 4
#define CC 256           // NHEADS * Hh
#define EPSN 1e-5f

// ---------------- scratch (device bss, no allocation) ----------------
__device__ __align__(16) float d_nacc[Nn * 8];        // deg, agg[5], easum[2]
__device__ __align__(16) float d_h[Nn * Hh];
__device__ __align__(16) float d_la[Nn * 2];
__device__ float d_sum1[2 * Hh];
__device__ float d_mu1[Hh], d_sc1[Hh];
__device__ __align__(16) float d_wT[Hh * CC];          // transposed gat_w: [k][t]
__device__ float d_weff[NHEADS * 2];
__device__ __align__(16) float d_xp[Nn * CC];
__device__ __align__(16) float d_asrc[Nn * NHEADS];
__device__ __align__(16) float d_adst[Nn * NHEADS];
__device__ __align__(16) float d_es[Nn * NHEADS];      // exp(alpha_self)
__device__ __align__(16) float d_den[Nn * NHEADS];     // softmax denominator
__device__ __align__(16) float d_expa[Ee * NHEADS];
__device__ __align__(16) float d_gnum[Nn * CC];
__device__ __align__(16) float d_g[Nn * CC];
__device__ float d_sum2[2 * CC];
__device__ float d_mu2[CC], d_sc2[CC];

// ---------------- helpers ----------------
__device__ __forceinline__ void red_add_v4(float* addr, float a, float b, float c, float d) {
    asm volatile("red.global.add.v4.f32 [%0], {%1,%2,%3,%4};"
                 :: "l"(addr), "f"(a), "f"(b), "f"(c), "f"(d) : "memory");
}
__device__ __forceinline__ float lrelu(float a) { return a > 0.f ? a : 0.2f * a; }
__device__ __forceinline__ float eluf(float a)  { return a > 0.f ? a : expm1f(a); }

// ---------------- k_prep: transpose gat_w + weff ----------------
__global__ void k_prep(const float* __restrict__ gat_w,
                       const float* __restrict__ att_e,
                       const float* __restrict__ gat_we) {
    int t = threadIdx.x;  // 256
    for (int k = 0; k < Hh; ++k)
        d_wT[k * CC + t] = gat_w[t * Hh + k];
    if (t < NHEADS * 2) {
        int h = t >> 1, kk = t & 1;
        float s = 0.f;
        for (int c = 0; c < Hh; ++c)
            s += gat_we[(h * Hh + c) * 2 + kk] * att_e[h * Hh + c];
        d_weff[t] = s;
    }
}

// ---------------- k_eagg: per-edge deg/agg/easum ----------------
__global__ void k_eagg(const int* __restrict__ src, const int* __restrict__ dst,
                       const float* __restrict__ x, const float* __restrict__ ea) {
    int e = blockIdx.x * blockDim.x + threadIdx.x;
    if (e >= Ee) return;
    int s = src[e], d = dst[e];
    const float* xs = x + s * 5;
    float x0 = xs[0], x1 = xs[1], x2 = xs[2], x3 = xs[3], x4 = xs[4];
    float2 e2 = ((const float2*)ea)[e];
    float* na = d_nacc + d * 8;
    red_add_v4(na,     1.f, x0, x1, x2);
    red_add_v4(na + 4, x3, x4, e2.x, e2.y);
}

// ---------------- k_node1: SAGE + norm1 stats ----------------
__global__ void k_node1(const float* __restrict__ x,
                        const float* __restrict__ wl,
                        const float* __restrict__ bl,
                        const float* __restrict__ wr) {
    __shared__ float sWl[Hh * 5], sWr[Hh * 5], sBl[Hh], ssum[Hh], ssum2[Hh];
    int tid = threadIdx.x;  // 256
    for (int i = tid; i < Hh * 5; i += 256) { sWl[i] = wl[i]; sWr[i] = wr[i]; }
    if (tid < Hh) { sBl[tid] = bl[tid]; ssum[tid] = 0.f; ssum2[tid] = 0.f; }
    __syncthreads();
    int nl = tid >> 6, c = tid & 63;
    int n = blockIdx.x * 4 + nl;
    float hv = 0.f;
    if (n < Nn) {
        const float* na = d_nacc + n * 8;
        float deg = fmaxf(na[0], 1.f);
        float inv = 1.f / deg;
        float a0 = na[1] * inv, a1 = na[2] * inv, a2 = na[3] * inv,
              a3 = na[4] * inv, a4 = na[5] * inv;
        const float* xr = x + n * 5;
        const float* wlr = sWl + c * 5;
        const float* wrr = sWr + c * 5;
        hv = sBl[c]
           + wlr[0]*a0 + wlr[1]*a1 + wlr[2]*a2 + wlr[3]*a3 + wlr[4]*a4
           + wrr[0]*xr[0] + wrr[1]*xr[1] + wrr[2]*xr[2] + wrr[3]*xr[3] + wrr[4]*xr[4];
        d_h[n * Hh + c] = hv;
        if (c < 2) d_la[n * 2 + c] = na[6 + c] * inv;
    }
    atomicAdd(&ssum[c], hv);
    atomicAdd(&ssum2[c], hv * hv);
    __syncthreads();
    if (tid < Hh) {
        atomicAdd(&d_sum1[tid], ssum[tid]);
        atomicAdd(&d_sum1[Hh + tid], ssum2[tid]);
    }
}

// ---------------- k_stats1 ----------------
__global__ void k_stats1(const float* __restrict__ w, const float* __restrict__ ms) {
    int c = threadIdx.x;  // 64
    float m  = d_sum1[c]      * (1.f / Nn);
    float m2 = d_sum1[Hh + c] * (1.f / Nn);
    float s = ms[c];
    float var = m2 - (2.f * s - s * s) * m * m;
    d_mu1[c] = s * m;
    d_sc1[c] = w[c] * rsqrtf(var + EPSN);
}

// ---------------- k_xp: norm1+ELU, xp = h1 @ W^T, a_src/a_dst ----------------
__global__ void k_xp(const float* __restrict__ n1b,
                     const float* __restrict__ att_s,
                     const float* __restrict__ att_d) {
    __shared__ float h1[8 * Hh];
    const int q = threadIdx.x;  // 64
    const int nb = blockIdx.x * 8;
    const float mu = d_mu1[q], sc = d_sc1[q], bb = n1b[q];
    #pragma unroll
    for (int i = 0; i < 8; ++i) {
        int n = nb + i;
        float v = 0.f;
        if (n < Nn) {
            float y = sc * (d_h[n * Hh + q] - mu) + bb;
            v = eluf(y);
        }
        h1[i * Hh + q] = v;
    }
    __syncthreads();
    float acc[8][4];
    #pragma unroll
    for (int i = 0; i < 8; ++i) { acc[i][0] = acc[i][1] = acc[i][2] = acc[i][3] = 0.f; }
    const float4* wt = (const float4*)d_wT;
    #pragma unroll 4
    for (int k = 0; k < Hh; ++k) {
        float4 w = wt[k * 64 + q];
        #pragma unroll
        for (int i = 0; i < 8; ++i) {
            float hk = h1[i * Hh + k];
            acc[i][0] = fmaf(w.x, hk, acc[i][0]);
            acc[i][1] = fmaf(w.y, hk, acc[i][1]);
            acc[i][2] = fmaf(w.z, hk, acc[i][2]);
            acc[i][3] = fmaf(w.w, hk, acc[i][3]);
        }
    }
    const int head = q >> 4;
    const int cb = (q & 15) * 4;
    float as0 = att_s[head * Hh + cb],     as1 = att_s[head * Hh + cb + 1],
          as2 = att_s[head * Hh + cb + 2], as3 = att_s[head * Hh + cb + 3];
    float ad0 = att_d[head * Hh + cb],     ad1 = att_d[head * Hh + cb + 1],
          ad2 = att_d[head * Hh + cb + 2], ad3 = att_d[head * Hh + cb + 3];
    #pragma unroll
    for (int i = 0; i < 8; ++i) {
        int n = nb + i;
        float4 o = make_float4(acc[i][0], acc[i][1], acc[i][2], acc[i][3]);
        float ps = o.x * as0 + o.y * as1 + o.z * as2 + o.w * as3;
        float pd = o.x * ad0 + o.y * ad1 + o.z * ad2 + o.w * ad3;
        #pragma unroll
        for (int off = 8; off > 0; off >>= 1) {
            ps += __shfl_xor_sync(0xffffffffu, ps, off);
            pd += __shfl_xor_sync(0xffffffffu, pd, off);
        }
        if (n < Nn) {
            ((float4*)d_xp)[n * 64 + q] = o;
            if ((q & 15) == 0) {
                d_asrc[n * NHEADS + head] = ps;
                d_adst[n * NHEADS + head] = pd;
            }
        }
    }
}

// ---------------- k_self: self-loop alpha, init denom ----------------
__global__ void k_self() {
    int n = blockIdx.x * blockDim.x + threadIdx.x;
    if (n >= Nn) return;
    float la0 = d_la[n * 2], la1 = d_la[n * 2 + 1];
    float4 as = ((const float4*)d_asrc)[n];
    float4 ad = ((const float4*)d_adst)[n];
    float4 r;
    r.x = expf(lrelu(as.x + ad.x + la0 * d_weff[0] + la1 * d_weff[1]));
    r.y = expf(lrelu(as.y + ad.y + la0 * d_weff[2] + la1 * d_weff[3]));
    r.z = expf(lrelu(as.z + ad.z + la0 * d_weff[4] + la1 * d_weff[5]));
    r.w = expf(lrelu(as.w + ad.w + la0 * d_weff[6] + la1 * d_weff[7]));
    ((float4*)d_es)[n]  = r;
    ((float4*)d_den)[n] = r;
}

// ---------------- k_alpha: per-edge exp(alpha), denom += ----------------
__global__ void k_alpha(const int* __restrict__ src, const int* __restrict__ dst,
                        const float* __restrict__ ea) {
    int e = blockIdx.x * blockDim.x + threadIdx.x;
    if (e >= Ee) return;
    int s = src[e], d = dst[e];
    float4 as = ((const float4*)d_asrc)[s];
    float4 ad = ((const float4*)d_adst)[d];
    float2 e2 = ((const float2*)ea)[e];
    float4 r;
    r.x = expf(lrelu(as.x + ad.x + e2.x * d_weff[0] + e2.y * d_weff[1]));
    r.y = expf(lrelu(as.y + ad.y + e2.x * d_weff[2] + e2.y * d_weff[3]));
    r.z = expf(lrelu(as.z + ad.z + e2.x * d_weff[4] + e2.y * d_weff[5]));
    r.w = expf(lrelu(as.w + ad.w + e2.x * d_weff[6] + e2.y * d_weff[7]));
    ((float4*)d_expa)[e] = r;
    red_add_v4(d_den + d * NHEADS, r.x, r.y, r.z, r.w);
}

// ---------------- k_msg: warp-per-edge scatter of xp[src]*expa ----------------
__global__ void k_msg(const int* __restrict__ src, const int* __restrict__ dst) {
    int e = blockIdx.x * 8 + (threadIdx.x >> 5);
    if (e >= Ee) return;
    int lane = threadIdx.x & 31;
    int s = src[e], d = dst[e];
    float exA = d_expa[e * 4 + (lane >> 4)];        // heads 0/1
    float exB = d_expa[e * 4 + 2 + (lane >> 4)];    // heads 2/3
    const float4* xs = (const float4*)(d_xp + s * CC);
    float4 vA = xs[lane];
    float4 vB = xs[lane + 32];
    float* gd = d_gnum + d * CC;
    red_add_v4(gd + lane * 4,       vA.x * exA, vA.y * exA, vA.z * exA, vA.w * exA);
    red_add_v4(gd + 128 + lane * 4, vB.x * exB, vB.y * exB, vB.z * exB, vB.w * exB);
}

// ---------------- k_g: finalize g, norm2 stats ----------------
__global__ void k_g(const float* __restrict__ gat_b) {
    int t = threadIdx.x;  // 256
    int head = t >> 6;
    float gb = gat_b[t];
    float s = 0.f, s2 = 0.f;
    int n0 = blockIdx.x * 64;
    for (int i = 0; i < 64; ++i) {
        int n = n0 + i;
        if (n >= Nn) break;
        float es = d_es[n * 4 + head];
        float den = d_den[n * 4 + head];
        float g = (d_gnum[n * CC + t] + es * d_xp[n * CC + t]) / den + gb;
        d_g[n * CC + t] = g;
        s += g; s2 += g * g;
    }
    atomicAdd(&d_sum2[t], s);
    atomicAdd(&d_sum2[CC + t], s2);
}

// ---------------- k_stats2 ----------------
__global__ void k_stats2(const float* __restrict__ w, const float* __restrict__ ms) {
    int c = threadIdx.x;  // 256
    float m  = d_sum2[c]      * (1.f / Nn);
    float m2 = d_sum2[CC + c] * (1.f / Nn);
    float s = ms[c];
    float var = m2 - (2.f * s - s * s) * m * m;
    d_mu2[c] = s * m;
    d_sc2[c] = w[c] * rsqrtf(var + EPSN);
}

// ---------------- k_out: norm2 + ELU + linear + relu ----------------
__global__ void k_out(const float* __restrict__ n2b,
                      const float* __restrict__ ow,
                      const float* __restrict__ ob,
                      float* __restrict__ out) {
    __shared__ float red[8][4];
    int n = blockIdx.x;
    int t = threadIdx.x;  // 256
    float y = d_sc2[t] * (d_g[n * CC + t] - d_mu2[t]) + n2b[t];
    y = eluf(y);
    float p0 = y * ow[t], p1 = y * ow[CC + t], p2 = y * ow[2 * CC + t], p3 = y * ow[3 * CC + t];
    #pragma unroll
    for (int off = 16; off > 0; off >>= 1) {
        p0 += __shfl_xor_sync(0xffffffffu, p0, off);
        p1 += __shfl_xor_sync(0xffffffffu, p1, off);
        p2 += __shfl_xor_sync(0xffffffffu, p2, off);
        p3 += __shfl_xor_sync(0xffffffffu, p3, off);
    }
    if ((t & 31) == 0) {
        int w = t >> 5;
        red[w][0] = p0; red[w][1] = p1; red[w][2] = p2; red[w][3] = p3;
    }
    __syncthreads();
    if (t < 4) {
        float s = ob[t];
        #pragma unroll
        for (int w = 0; w < 8; ++w) s += red[w][t];
        out[n * 4 + t] = fmaxf(s, 0.f);
    }
}

// ---------------- host ----------------
extern "C" void kernel_launch(void* const* d_in, const int* in_sizes, int n_in,
                              void* d_out, int out_size) {
    const float* x     = (const float*)d_in[0];
    const float* ea    = (const float*)d_in[1];
    const float* swl   = (const float*)d_in[2];
    const float* sbl   = (const float*)d_in[3];
    const float* swr   = (const float*)d_in[4];
    const float* n1w   = (const float*)d_in[5];
    const float* n1b   = (const float*)d_in[6];
    const float* n1ms  = (const float*)d_in[7];
    const float* gatw  = (const float*)d_in[8];
    const float* atts  = (const float*)d_in[9];
    const float* attd  = (const float*)d_in[10];
    const float* atte  = (const float*)d_in[11];
    const float* gatwe = (const float*)d_in[12];
    const float* gatb  = (const float*)d_in[13];
    const float* n2w   = (const float*)d_in[14];
    const float* n2b   = (const float*)d_in[15];
    const float* n2ms  = (const float*)d_in[16];
    const float* outw  = (const float*)d_in[17];
    const float* outb  = (const float*)d_in[18];
    const int*   eidx  = (const int*)d_in[19];
    const int* src = eidx;
    const int* dst = eidx + Ee;
    float* out = (float*)d_out;

    void *p_nacc, *p_gnum, *p_s1, *p_s2;
    cudaGetSymbolAddress(&p_nacc, d_nacc);
    cudaGetSymbolAddress(&p_gnum, d_gnum);
    cudaGetSymbolAddress(&p_s1, d_sum1);
    cudaGetSymbolAddress(&p_s2, d_sum2);
    cudaMemsetAsync(p_nacc, 0, sizeof(float) * Nn * 8);
    cudaMemsetAsync(p_gnum, 0, sizeof(float) * (size_t)Nn * CC);
    cudaMemsetAsync(p_s1, 0, sizeof(float) * 2 * Hh);
    cudaMemsetAsync(p_s2, 0, sizeof(float) * 2 * CC);

    k_prep<<<1, 256>>>(gatw, atte, gatwe);
    k_eagg<<<(Ee + 255) / 256, 256>>>(src, dst, x, ea);
    k_node1<<<(Nn + 3) / 4, 256>>>(x, swl, sbl, swr);
    k_stats1<<<1, 64>>>(n1w, n1ms);
    k_xp<<<(Nn + 7) / 8, 64>>>(n1b, atts, attd);
    k_self<<<(Nn + 255) / 256, 256>>>();
    k_alpha<<<(Ee + 255) / 256, 256>>>(src, dst, ea);
    k_msg<<<(Ee + 7) / 8, 256>>>(src, dst);
    k_g<<<(Nn + 63) / 64, 256>>>(gatb);
    k_stats2<<<1, 256>>>(n2w, n2ms);
    k_out<<<Nn, 256>>>(n2b, outw, outb, out);
}